// round 12
// baseline (speedup 1.0000x reference)
#include <cuda_runtime.h>
#include <cuda_fp16.h>
#include <cstdint>
#include <math.h>

// ---------------- problem constants ----------------
#define T_TOK 4096
#define HID   1024
#define INTER 4096
#define NEXP  8

// ---------------- GEMM tiling ----------------
#define TM 128           // CTA M (both GEMMs)
#define TN 128           // CTA N (both GEMMs)
#define CK 64            // K halves per chunk (128B rows)
#define STAGES 3
#define MAX_TILES 72
#define MAX_SLOTS (MAX_TILES * TM)
#define CONV_BLKS 2048                      // leading router-launch blocks converting w1
#define CONV_ROWS 2                         // leading gemm1 blockIdx.y rows converting w2
#define W_ELEMS4 (NEXP * INTER * HID / 4)   // float4 count per weight tensor

#define STAGE_BYTES 32768                   // A 16KB + B 16KB
#define SMEM_RTOK   (STAGES * STAGE_BYTES)
#define SMEM_TOTAL  (SMEM_RTOK + 512)

// ---------------- device scratch (16B-aligned) ----------------
__device__ __align__(16) int    g_counts[NEXP];
__device__ __align__(16) int    g_cursor[NEXP];
__device__ __align__(16) int    g_poff[NEXP];
__device__ __align__(16) int    g_num_tiles_pad[4];
__device__ __align__(16) int    g_tile_expert[MAX_TILES];
__device__ __align__(16) int    g_slot_token[MAX_SLOTS];
__device__ __align__(16) int    g_top_idx[T_TOK * 2];
__device__ __align__(16) float  g_top_w[T_TOK * 2];
__device__ __align__(16) int    g_tok_slot[T_TOK * 2];
__device__ __align__(16) __half g_xh[(size_t)T_TOK * HID];          // fp16 activations
__device__ __align__(16) __half g_w1h[(size_t)NEXP * INTER * HID];  // fp16 w1
__device__ __align__(16) __half g_w2h[(size_t)NEXP * HID * INTER];  // fp16 w2
__device__ __align__(16) __half g_Hh[(size_t)MAX_SLOTS * INTER];    // fp16 gelu(x@w1^T)
__device__ __align__(16) float  g_Y[(size_t)MAX_SLOTS * HID];

#define g_num_tiles (g_num_tiles_pad[0])

// ---------------- PTX helpers ----------------
__device__ __forceinline__ uint32_t smem_to_u32(const void* p) {
    uint32_t a;
    asm("{ .reg .u64 t; cvta.to.shared.u64 t, %1; cvt.u32.u64 %0, t; }" : "=r"(a) : "l"(p));
    return a;
}
#define CP_ASYNC16(dst, src) \
    asm volatile("cp.async.cg.shared.global [%0], [%1], 16;" :: "r"(dst), "l"(src))
#define CP_COMMIT() asm volatile("cp.async.commit_group;" ::: "memory")
#define CP_WAIT(n)  asm volatile("cp.async.wait_group %0;" :: "n"(n) : "memory")

__device__ __forceinline__ void ldsm_x4(uint32_t& r0, uint32_t& r1, uint32_t& r2, uint32_t& r3,
                                        uint32_t addr) {
    asm volatile("ldmatrix.sync.aligned.m8n8.x4.shared.b16 {%0,%1,%2,%3}, [%4];"
                 : "=r"(r0), "=r"(r1), "=r"(r2), "=r"(r3) : "r"(addr));
}
#define MMA_F16(c, a0, a1, a2, a3, b0, b1)                                      \
    asm volatile("mma.sync.aligned.m16n8k16.row.col.f32.f16.f16.f32 "           \
                 "{%0,%1,%2,%3}, {%4,%5,%6,%7}, {%8,%9}, {%0,%1,%2,%3};"        \
                 : "+f"(c[0]), "+f"(c[1]), "+f"(c[2]), "+f"(c[3])               \
                 : "r"(a0), "r"(a1), "r"(a2), "r"(a3), "r"(b0), "r"(b1))

#define SWZ(off) ((off) ^ (((off) >> 3) & 0x70))

__device__ __forceinline__ void conv_chunk(const float4* __restrict__ s,
                                           __half2* __restrict__ d, int i) {
    float4 v = s[i];
    d[2 * i]     = __floats2half2_rn(v.x, v.y);
    d[2 * i + 1] = __floats2half2_rn(v.z, v.w);
}

// ---------------- stage 0: reset ----------------
__global__ void init_kernel() {
    if (threadIdx.x < NEXP) { g_counts[threadIdx.x] = 0; g_cursor[threadIdx.x] = 0; }
}

// ---------------- stage 1: router (+ fp16 act write), fused w1 convert ----------------
__global__ void router_kernel(const float* __restrict__ x,
                              const float* __restrict__ gw,
                              float* __restrict__ logits_out,
                              const float* __restrict__ w1src) {
    if (blockIdx.x < CONV_BLKS) {   // leading blocks: w1 fp32 -> fp16
        const float4* s = (const float4*)w1src;
        __half2* d = (__half2*)g_w1h;
        #pragma unroll 4
        for (int i = blockIdx.x * blockDim.x + threadIdx.x; i < W_ELEMS4;
             i += CONV_BLKS * blockDim.x)
            conv_chunk(s, d, i);
        return;
    }
    __shared__ float xs[HID];
    __shared__ float ls[NEXP];
    int t = blockIdx.x - CONV_BLKS;
    const float4* xp = (const float4*)(x + (size_t)t * HID);
    __half2* xh = (__half2*)(g_xh + (size_t)t * HID);
    for (int i = threadIdx.x; i < HID / 4; i += blockDim.x) {
        float4 v = xp[i];
        ((float4*)xs)[i] = v;
        xh[2 * i]     = __floats2half2_rn(v.x, v.y);
        xh[2 * i + 1] = __floats2half2_rn(v.z, v.w);
    }
    __syncthreads();

    int w = threadIdx.x >> 5, lane = threadIdx.x & 31;
    if (w < NEXP) {
        const float* g = gw + (size_t)w * HID;
        float s = 0.f;
        for (int i = lane; i < HID; i += 32) s += xs[i] * g[i];
        #pragma unroll
        for (int o = 16; o; o >>= 1) s += __shfl_xor_sync(0xffffffffu, s, o);
        if (lane == 0) { ls[w] = s; logits_out[(size_t)t * NEXP + w] = s; }
    }
    __syncthreads();

    if (threadIdx.x == 0) {
        int i0 = 0; float v0 = ls[0];
        #pragma unroll
        for (int e = 1; e < NEXP; e++) if (ls[e] > v0) { v0 = ls[e]; i0 = e; }
        int i1 = -1; float v1 = -3.4e38f;
        #pragma unroll
        for (int e = 0; e < NEXP; e++) if (e != i0 && ls[e] > v1) { v1 = ls[e]; i1 = e; }
        float w1v = 1.f / (1.f + expf(v0 - v1));
        float w0v = 1.f - w1v;
        g_top_idx[2 * t] = i0;  g_top_idx[2 * t + 1] = i1;
        g_top_w[2 * t] = w0v;   g_top_w[2 * t + 1] = w1v;
        atomicAdd(&g_counts[i0], 1);
        atomicAdd(&g_counts[i1], 1);
    }
}

// ---------------- stage 2: scatter (+ offsets publish) ----------------
__global__ void scatter_kernel() {
    int poffs[NEXP];
    {
        int pad = 0;
        #pragma unroll
        for (int e = 0; e < NEXP; e++) {
            poffs[e] = pad;
            pad += ((g_counts[e] + TM - 1) / TM) * TM;
        }
    }
    if (blockIdx.x == 0 && threadIdx.x == 0) {
        int nt = 0;
        for (int e = 0; e < NEXP; e++) {
            g_poff[e] = poffs[e];
            int tiles = (g_counts[e] + TM - 1) / TM;
            for (int j = 0; j < tiles; j++) g_tile_expert[nt++] = e;
        }
        g_num_tiles = nt;
    }
    int t = blockIdx.x * blockDim.x + threadIdx.x;
    if (t >= T_TOK) return;
    #pragma unroll
    for (int j = 0; j < 2; j++) {
        int e = g_top_idx[2 * t + j];
        int p = atomicAdd(&g_cursor[e], 1);
        int slot = poffs[e] + p;
        g_slot_token[slot] = t;
        g_tok_slot[2 * t + j] = slot;
    }
}

// ---------------- stage 3: GEMM1 (128 thr, 64x64 warp tiles, frag double-buffer) ----------------
// g_Hh = half( gelu( gather(g_xh) @ w1h[e]^T ) )   K=1024, Ntot=4096
// first CONV_ROWS blockIdx.y rows convert w2 fp32->fp16 concurrently
__global__ void __launch_bounds__(128, 2)
gemm1_f16(const __half* __restrict__ Asrc, const __half* __restrict__ W,
          const float* __restrict__ csrc, __half* __restrict__ cdst) {
    constexpr int KDIM = HID;
    constexpr int NTOT = INTER;
    constexpr int NC = KDIM / CK;   // 16

    int tid = threadIdx.x;

    if (blockIdx.y < CONV_ROWS) {
        const float4* s = (const float4*)csrc;
        __half2* d = (__half2*)cdst;
        int cid = blockIdx.y * gridDim.x + blockIdx.x;
        int nth = CONV_ROWS * gridDim.x * 128;
        #pragma unroll 4
        for (int i = cid * 128 + tid; i < W_ELEMS4; i += nth)
            conv_chunk(s, d, i);
        return;
    }
    int mt = blockIdx.y - CONV_ROWS;
    if (mt >= g_num_tiles) return;

    extern __shared__ char smem[];
    uint32_t sb = smem_to_u32(smem);
    int lane = tid & 31, wid = tid >> 5;   // 4 warps

    int e = g_tile_expert[mt];
    int row_base = mt * TM;
    const __half* B = W + (size_t)e * NTOT * KDIM + (size_t)(blockIdx.x * TN) * KDIM;

    int* rtok = (int*)(smem + SMEM_RTOK);
    {
        int gr = row_base + tid;
        int cnt = g_counts[e], poff = g_poff[e];
        rtok[tid] = (gr - poff) < cnt ? g_slot_token[gr] : 0;
    }
    __syncthreads();

    // per-thread cp.async: 8 A + 8 B 16B-chunks (128 rows x 8 chunks / 128 thr)
    const __half* asrc[8]; const __half* bsrc[8];
    uint32_t adst[8], bdst[8];
    #pragma unroll
    for (int i = 0; i < 8; i++) {
        int f = tid + i * 128;
        int row = f >> 3, c = f & 7;
        asrc[i] = Asrc + (size_t)rtok[row] * KDIM + c * 8;
        adst[i] = sb + SWZ(row * 128 + c * 16);
        bsrc[i] = B + (size_t)row * KDIM + c * 8;
        bdst[i] = sb + 16384u + SWZ(row * 128 + c * 16);
    }

    auto issue = [&](int kc, int s) {
        uint32_t off = (uint32_t)s * STAGE_BYTES;
        size_t koff = (size_t)kc * CK;
        #pragma unroll
        for (int i = 0; i < 8; i++) {
            CP_ASYNC16(adst[i] + off, (const void*)(asrc[i] + koff));
            CP_ASYNC16(bdst[i] + off, (const void*)(bsrc[i] + koff));
        }
    };

    // warp tile 64(M) x 64(N); warp grid 2 x 2
    int wm = (wid & 1) * 64;
    int wn = (wid >> 1) * 64;
    int qr = lane >> 2, qc = lane & 3;

    uint32_t arow[4], brow[4];
    #pragma unroll
    for (int mi = 0; mi < 4; mi++)
        arow[mi] = (uint32_t)(wm + mi * 16 + (lane & 15)) * 128u + ((lane >> 4) << 4);
    #pragma unroll
    for (int nb = 0; nb < 4; nb++)
        brow[nb] = (uint32_t)(wn + nb * 16 + ((lane >> 4) & 1) * 8 + (lane & 7)) * 128u
                   + (((lane >> 3) & 1) << 4);

    float c[4][8][4];
    #pragma unroll
    for (int mi = 0; mi < 4; mi++)
        #pragma unroll
        for (int ni = 0; ni < 8; ni++)
            #pragma unroll
            for (int j = 0; j < 4; j++) c[mi][ni][j] = 0.f;

    issue(0, 0); CP_COMMIT();
    issue(1, 1); CP_COMMIT();

    uint32_t a[2][4][4], b[2][4][4];
    for (int kc = 0; kc < NC; kc++) {
        CP_WAIT(1);
        __syncthreads();
        int nk = kc + STAGES - 1;
        if (nk < NC) issue(nk, nk % STAGES);
        CP_COMMIT();

        uint32_t soff = (uint32_t)(kc % STAGES) * STAGE_BYTES;
        uint32_t abase = sb + soff;
        uint32_t bbase = sb + soff + 16384u;

        // prefetch ks=0 fragments
        #pragma unroll
        for (int mi = 0; mi < 4; mi++)
            ldsm_x4(a[0][mi][0], a[0][mi][1], a[0][mi][2], a[0][mi][3],
                    abase + SWZ(arow[mi]));
        #pragma unroll
        for (int nb = 0; nb < 4; nb++)
            ldsm_x4(b[0][nb][0], b[0][nb][1], b[0][nb][2], b[0][nb][3],
                    bbase + SWZ(brow[nb]));

        #pragma unroll
        for (int ks = 0; ks < 4; ks++) {
            int cur = ks & 1, nxt = cur ^ 1;
            if (ks < 3) {   // prefetch next ks fragments before the mma block
                #pragma unroll
                for (int mi = 0; mi < 4; mi++)
                    ldsm_x4(a[nxt][mi][0], a[nxt][mi][1], a[nxt][mi][2], a[nxt][mi][3],
                            abase + SWZ(arow[mi] + (ks + 1) * 32));
                #pragma unroll
                for (int nb = 0; nb < 4; nb++)
                    ldsm_x4(b[nxt][nb][0], b[nxt][nb][1], b[nxt][nb][2], b[nxt][nb][3],
                            bbase + SWZ(brow[nb] + (ks + 1) * 32));
            }
            #pragma unroll
            for (int mi = 0; mi < 4; mi++) {
                #pragma unroll
                for (int nb = 0; nb < 4; nb++) {
                    MMA_F16(c[mi][nb * 2 + 0], a[cur][mi][0], a[cur][mi][1],
                            a[cur][mi][2], a[cur][mi][3], b[cur][nb][0], b[cur][nb][1]);
                    MMA_F16(c[mi][nb * 2 + 1], a[cur][mi][0], a[cur][mi][1],
                            a[cur][mi][2], a[cur][mi][3], b[cur][nb][2], b[cur][nb][3]);
                }
            }
        }
    }

    #pragma unroll
    for (int mi = 0; mi < 4; mi++) {
        #pragma unroll
        for (int ni = 0; ni < 8; ni++) {
            int r0 = row_base + wm + mi * 16 + qr;
            int col = blockIdx.x * TN + wn + ni * 8 + 2 * qc;
            float v0 = c[mi][ni][0], v1 = c[mi][ni][1];
            float v2 = c[mi][ni][2], v3 = c[mi][ni][3];
            v0 *= normcdff(v0); v1 *= normcdff(v1);
            v2 *= normcdff(v2); v3 *= normcdff(v3);
            *(__half2*)(g_Hh + (size_t)r0 * NTOT + col)       = __floats2half2_rn(v0, v1);
            *(__half2*)(g_Hh + (size_t)(r0 + 8) * NTOT + col) = __floats2half2_rn(v2, v3);
        }
    }
}

// ---------------- stage 4: GEMM2 (128 thr, 64x64 warp tiles, frag double-buffer) ----------------
// g_Y = g_Hh @ w2h[e]^T     K=4096, Ntot=1024
__global__ void __launch_bounds__(128, 2)
gemm2_f16(const __half* __restrict__ Asrc, const __half* __restrict__ W) {
    constexpr int KDIM = INTER;
    constexpr int NTOT = HID;
    constexpr int NC = KDIM / CK;     // 64

    int tid = threadIdx.x;
    int mt = blockIdx.y;
    if (mt >= g_num_tiles) return;

    extern __shared__ char smem[];
    uint32_t sb = smem_to_u32(smem);
    int lane = tid & 31, wid = tid >> 5;   // 4 warps

    int row_base = mt * TM;
    int e = g_tile_expert[mt];
    const __half* B = W + (size_t)e * NTOT * KDIM + (size_t)(blockIdx.x * TN) * KDIM;

    const __half* asrc[8]; const __half* bsrc[8];
    uint32_t adst[8], bdst[8];
    #pragma unroll
    for (int i = 0; i < 8; i++) {
        int f = tid + i * 128;
        int row = f >> 3, c = f & 7;
        asrc[i] = Asrc + (size_t)(row_base + row) * KDIM + c * 8;
        adst[i] = sb + SWZ(row * 128 + c * 16);
        bsrc[i] = B + (size_t)row * KDIM + c * 8;
        bdst[i] = sb + 16384u + SWZ(row * 128 + c * 16);
    }

    auto issue = [&](int kc, int s) {
        uint32_t off = (uint32_t)s * STAGE_BYTES;
        size_t koff = (size_t)kc * CK;
        #pragma unroll
        for (int i = 0; i < 8; i++) {
            CP_ASYNC16(adst[i] + off, (const void*)(asrc[i] + koff));
            CP_ASYNC16(bdst[i] + off, (const void*)(bsrc[i] + koff));
        }
    };

    int wm = (wid & 1) * 64;
    int wn = (wid >> 1) * 64;
    int qr = lane >> 2, qc = lane & 3;

    uint32_t arow[4], brow[4];
    #pragma unroll
    for (int mi = 0; mi < 4; mi++)
        arow[mi] = (uint32_t)(wm + mi * 16 + (lane & 15)) * 128u + ((lane >> 4) << 4);
    #pragma unroll
    for (int nb = 0; nb < 4; nb++)
        brow[nb] = (uint32_t)(wn + nb * 16 + ((lane >> 4) & 1) * 8 + (lane & 7)) * 128u
                   + (((lane >> 3) & 1) << 4);

    float c[4][8][4];
    #pragma unroll
    for (int mi = 0; mi < 4; mi++)
        #pragma unroll
        for (int ni = 0; ni < 8; ni++)
            #pragma unroll
            for (int j = 0; j < 4; j++) c[mi][ni][j] = 0.f;

    issue(0, 0); CP_COMMIT();
    issue(1, 1); CP_COMMIT();

    uint32_t a[2][4][4], b[2][4][4];
    for (int kc = 0; kc < NC; kc++) {
        CP_WAIT(1);
        __syncthreads();
        int nk = kc + STAGES - 1;
        if (nk < NC) issue(nk, nk % STAGES);
        CP_COMMIT();

        uint32_t soff = (uint32_t)(kc % STAGES) * STAGE_BYTES;
        uint32_t abase = sb + soff;
        uint32_t bbase = sb + soff + 16384u;

        #pragma unroll
        for (int mi = 0; mi < 4; mi++)
            ldsm_x4(a[0][mi][0], a[0][mi][1], a[0][mi][2], a[0][mi][3],
                    abase + SWZ(arow[mi]));
        #pragma unroll
        for (int nb = 0; nb < 4; nb++)
            ldsm_x4(b[0][nb][0], b[0][nb][1], b[0][nb][2], b[0][nb][3],
                    bbase + SWZ(brow[nb]));

        #pragma unroll
        for (int ks = 0; ks < 4; ks++) {
            int cur = ks & 1, nxt = cur ^ 1;
            if (ks < 3) {
                #pragma unroll
                for (int mi = 0; mi < 4; mi++)
                    ldsm_x4(a[nxt][mi][0], a[nxt][mi][1], a[nxt][mi][2], a[nxt][mi][3],
                            abase + SWZ(arow[mi] + (ks + 1) * 32));
                #pragma unroll
                for (int nb = 0; nb < 4; nb++)
                    ldsm_x4(b[nxt][nb][0], b[nxt][nb][1], b[nxt][nb][2], b[nxt][nb][3],
                            bbase + SWZ(brow[nb] + (ks + 1) * 32));
            }
            #pragma unroll
            for (int mi = 0; mi < 4; mi++) {
                #pragma unroll
                for (int nb = 0; nb < 4; nb++) {
                    MMA_F16(c[mi][nb * 2 + 0], a[cur][mi][0], a[cur][mi][1],
                            a[cur][mi][2], a[cur][mi][3], b[cur][nb][0], b[cur][nb][1]);
                    MMA_F16(c[mi][nb * 2 + 1], a[cur][mi][0], a[cur][mi][1],
                            a[cur][mi][2], a[cur][mi][3], b[cur][nb][2], b[cur][nb][3]);
                }
            }
        }
    }

    #pragma unroll
    for (int mi = 0; mi < 4; mi++) {
        #pragma unroll
        for (int ni = 0; ni < 8; ni++) {
            int r0 = row_base + wm + mi * 16 + qr;
            int col = blockIdx.x * TN + wn + ni * 8 + 2 * qc;
            *(float2*)(g_Y + (size_t)r0 * NTOT + col) =
                make_float2(c[mi][ni][0], c[mi][ni][1]);
            *(float2*)(g_Y + (size_t)(r0 + 8) * NTOT + col) =
                make_float2(c[mi][ni][2], c[mi][ni][3]);
        }
    }
}

// ---------------- stage 5: combine ----------------
__global__ void combine_kernel(float* __restrict__ out) {
    int t = blockIdx.x;
    int s0 = g_tok_slot[2 * t], s1 = g_tok_slot[2 * t + 1];
    float w0 = g_top_w[2 * t], w1 = g_top_w[2 * t + 1];
    const float4* y0 = (const float4*)(g_Y + (size_t)s0 * HID);
    const float4* y1 = (const float4*)(g_Y + (size_t)s1 * HID);
    float4* o = (float4*)(out + (size_t)t * HID);
    int i = threadIdx.x;
    float4 a = y0[i], b = y1[i];
    o[i] = make_float4(w0 * a.x + w1 * b.x, w0 * a.y + w1 * b.y,
                       w0 * a.z + w1 * b.z, w0 * a.w + w1 * b.w);
}

// ---------------- launch ----------------
extern "C" void kernel_launch(void* const* d_in, const int* in_sizes, int n_in,
                              void* d_out, int out_size) {
    const float* x  = (const float*)d_in[0];
    const float* gw = (const float*)d_in[1];
    const float* w1 = (const float*)d_in[2];
    const float* w2 = (const float*)d_in[3];
    float* out = (float*)d_out;
    float* logits = out + (size_t)T_TOK * HID;

    cudaFuncSetAttribute(gemm1_f16, cudaFuncAttributeMaxDynamicSharedMemorySize, SMEM_TOTAL);
    cudaFuncSetAttribute(gemm2_f16, cudaFuncAttributeMaxDynamicSharedMemorySize, SMEM_TOTAL);

    __half* w1h; cudaGetSymbolAddress((void**)&w1h, g_w1h);
    __half* w2h; cudaGetSymbolAddress((void**)&w2h, g_w2h);
    __half* xh;  cudaGetSymbolAddress((void**)&xh,  g_xh);
    __half* Hh;  cudaGetSymbolAddress((void**)&Hh,  g_Hh);

    init_kernel<<<1, 32>>>();
    router_kernel<<<T_TOK + CONV_BLKS, 256>>>(x, gw, logits, w1);
    scatter_kernel<<<16, 256>>>();
    gemm1_f16<<<dim3(INTER / TN, MAX_TILES + CONV_ROWS), 128, SMEM_TOTAL>>>(xh, w1h, w2, w2h);
    gemm2_f16<<<dim3(HID / TN, MAX_TILES), 128, SMEM_TOTAL>>>(Hh, w2h);
    combine_kernel<<<T_TOK, 256>>>(out);
}

// round 13
// speedup vs baseline: 1.1173x; 1.1173x over previous
#include <cuda_runtime.h>
#include <cuda_fp16.h>
#include <cstdint>
#include <math.h>

// ---------------- problem constants ----------------
#define T_TOK 4096
#define HID   1024
#define INTER 4096
#define NEXP  8

// ---------------- GEMM tiling ----------------
#define TM 128           // CTA M (both GEMMs)
#define TN 128           // CTA N (gemm2)
#define TN1 64           // CTA N (gemm1)
#define CK 64            // K halves per chunk (128B rows)
#define STAGES 3
#define MAX_TILES 72
#define MAX_SLOTS (MAX_TILES * TM)
#define CONV_BLKS 2048                      // leading router-launch blocks converting w1
#define CONV_ROWS 1                         // leading gemm1 blockIdx.y rows converting w2
#define W_ELEMS4 (NEXP * INTER * HID / 4)   // float4 count per weight tensor

// gemm2 smem: A 16KB + B 16KB per stage
#define STAGE_BYTES 32768
#define SMEM_RTOK   (STAGES * STAGE_BYTES)
#define SMEM_TOTAL  (SMEM_RTOK + 512)
// gemm1 smem: A 16KB + B 8KB per stage (TN1=64)
#define STAGE1_BYTES 24576
#define SMEM1_RTOK  (STAGES * STAGE1_BYTES)
#define SMEM1_TOTAL (SMEM1_RTOK + 512)

// ---------------- device scratch (16B-aligned) ----------------
__device__ __align__(16) int    g_counts[NEXP];
__device__ __align__(16) int    g_cursor[NEXP];
__device__ __align__(16) int    g_poff[NEXP];
__device__ __align__(16) int    g_num_tiles_pad[4];
__device__ __align__(16) int    g_tile_expert[MAX_TILES];
__device__ __align__(16) int    g_slot_token[MAX_SLOTS];
__device__ __align__(16) int    g_top_idx[T_TOK * 2];
__device__ __align__(16) float  g_top_w[T_TOK * 2];
__device__ __align__(16) int    g_tok_slot[T_TOK * 2];
__device__ __align__(16) __half g_xh[(size_t)T_TOK * HID];          // fp16 activations
__device__ __align__(16) __half g_w1h[(size_t)NEXP * INTER * HID];  // fp16 w1
__device__ __align__(16) __half g_w2h[(size_t)NEXP * HID * INTER];  // fp16 w2
__device__ __align__(16) __half g_Hh[(size_t)MAX_SLOTS * INTER];    // fp16 gelu(x@w1^T)
__device__ __align__(16) float  g_Y[(size_t)MAX_SLOTS * HID];

#define g_num_tiles (g_num_tiles_pad[0])

// ---------------- PTX helpers ----------------
__device__ __forceinline__ uint32_t smem_to_u32(const void* p) {
    uint32_t a;
    asm("{ .reg .u64 t; cvta.to.shared.u64 t, %1; cvt.u32.u64 %0, t; }" : "=r"(a) : "l"(p));
    return a;
}
#define CP_ASYNC16(dst, src) \
    asm volatile("cp.async.cg.shared.global [%0], [%1], 16;" :: "r"(dst), "l"(src))
#define CP_COMMIT() asm volatile("cp.async.commit_group;" ::: "memory")
#define CP_WAIT(n)  asm volatile("cp.async.wait_group %0;" :: "n"(n) : "memory")

__device__ __forceinline__ void ldsm_x4(uint32_t& r0, uint32_t& r1, uint32_t& r2, uint32_t& r3,
                                        uint32_t addr) {
    asm volatile("ldmatrix.sync.aligned.m8n8.x4.shared.b16 {%0,%1,%2,%3}, [%4];"
                 : "=r"(r0), "=r"(r1), "=r"(r2), "=r"(r3) : "r"(addr));
}
#define MMA_F16(c, a0, a1, a2, a3, b0, b1)                                      \
    asm volatile("mma.sync.aligned.m16n8k16.row.col.f32.f16.f16.f32 "           \
                 "{%0,%1,%2,%3}, {%4,%5,%6,%7}, {%8,%9}, {%0,%1,%2,%3};"        \
                 : "+f"(c[0]), "+f"(c[1]), "+f"(c[2]), "+f"(c[3])               \
                 : "r"(a0), "r"(a1), "r"(a2), "r"(a3), "r"(b0), "r"(b1))

#define SWZ(off) ((off) ^ (((off) >> 3) & 0x70))

__device__ __forceinline__ void conv_chunk(const float4* __restrict__ s,
                                           __half2* __restrict__ d, int i) {
    float4 v = s[i];
    d[2 * i]     = __floats2half2_rn(v.x, v.y);
    d[2 * i + 1] = __floats2half2_rn(v.z, v.w);
}

// ---------------- stage 0: reset ----------------
__global__ void init_kernel() {
    if (threadIdx.x < NEXP) { g_counts[threadIdx.x] = 0; g_cursor[threadIdx.x] = 0; }
}

// ---------------- stage 1: router (+ fp16 act write), fused w1 convert ----------------
__global__ void router_kernel(const float* __restrict__ x,
                              const float* __restrict__ gw,
                              float* __restrict__ logits_out,
                              const float* __restrict__ w1src) {
    if (blockIdx.x < CONV_BLKS) {   // leading blocks: w1 fp32 -> fp16
        const float4* s = (const float4*)w1src;
        __half2* d = (__half2*)g_w1h;
        #pragma unroll 4
        for (int i = blockIdx.x * blockDim.x + threadIdx.x; i < W_ELEMS4;
             i += CONV_BLKS * blockDim.x)
            conv_chunk(s, d, i);
        return;
    }
    __shared__ float xs[HID];
    __shared__ float ls[NEXP];
    int t = blockIdx.x - CONV_BLKS;
    const float4* xp = (const float4*)(x + (size_t)t * HID);
    __half2* xh = (__half2*)(g_xh + (size_t)t * HID);
    for (int i = threadIdx.x; i < HID / 4; i += blockDim.x) {
        float4 v = xp[i];
        ((float4*)xs)[i] = v;
        xh[2 * i]     = __floats2half2_rn(v.x, v.y);
        xh[2 * i + 1] = __floats2half2_rn(v.z, v.w);
    }
    __syncthreads();

    int w = threadIdx.x >> 5, lane = threadIdx.x & 31;
    if (w < NEXP) {
        const float* g = gw + (size_t)w * HID;
        float s = 0.f;
        for (int i = lane; i < HID; i += 32) s += xs[i] * g[i];
        #pragma unroll
        for (int o = 16; o; o >>= 1) s += __shfl_xor_sync(0xffffffffu, s, o);
        if (lane == 0) { ls[w] = s; logits_out[(size_t)t * NEXP + w] = s; }
    }
    __syncthreads();

    if (threadIdx.x == 0) {
        int i0 = 0; float v0 = ls[0];
        #pragma unroll
        for (int e = 1; e < NEXP; e++) if (ls[e] > v0) { v0 = ls[e]; i0 = e; }
        int i1 = -1; float v1 = -3.4e38f;
        #pragma unroll
        for (int e = 0; e < NEXP; e++) if (e != i0 && ls[e] > v1) { v1 = ls[e]; i1 = e; }
        float w1v = 1.f / (1.f + expf(v0 - v1));
        float w0v = 1.f - w1v;
        g_top_idx[2 * t] = i0;  g_top_idx[2 * t + 1] = i1;
        g_top_w[2 * t] = w0v;   g_top_w[2 * t + 1] = w1v;
        atomicAdd(&g_counts[i0], 1);
        atomicAdd(&g_counts[i1], 1);
    }
}

// ---------------- stage 2: scatter (+ offsets publish) ----------------
__global__ void scatter_kernel() {
    int poffs[NEXP];
    {
        int pad = 0;
        #pragma unroll
        for (int e = 0; e < NEXP; e++) {
            poffs[e] = pad;
            pad += ((g_counts[e] + TM - 1) / TM) * TM;
        }
    }
    if (blockIdx.x == 0 && threadIdx.x == 0) {
        int nt = 0;
        for (int e = 0; e < NEXP; e++) {
            g_poff[e] = poffs[e];
            int tiles = (g_counts[e] + TM - 1) / TM;
            for (int j = 0; j < tiles; j++) g_tile_expert[nt++] = e;
        }
        g_num_tiles = nt;
    }
    int t = blockIdx.x * blockDim.x + threadIdx.x;
    if (t >= T_TOK) return;
    #pragma unroll
    for (int j = 0; j < 2; j++) {
        int e = g_top_idx[2 * t + j];
        int p = atomicAdd(&g_cursor[e], 1);
        int slot = poffs[e] + p;
        g_slot_token[slot] = t;
        g_tok_slot[2 * t + j] = slot;
    }
}

// ---------------- stage 3: GEMM1 (256 thr, 8 warps x 32x32 tiles, 3 CTA/SM) ----------------
// g_Hh = half( gelu( gather(g_xh) @ w1h[e]^T ) )   CTA tile 128x64, K=1024
// first CONV_ROWS blockIdx.y rows convert w2 fp32->fp16 concurrently
__global__ void __launch_bounds__(256, 3)
gemm1_f16(const __half* __restrict__ Asrc, const __half* __restrict__ W,
          const float* __restrict__ csrc, __half* __restrict__ cdst) {
    constexpr int KDIM = HID;
    constexpr int NTOT = INTER;
    constexpr int NC = KDIM / CK;   // 16

    int tid = threadIdx.x;

    if (blockIdx.y < CONV_ROWS) {
        const float4* s = (const float4*)csrc;
        __half2* d = (__half2*)cdst;
        int cid = blockIdx.x;
        int nth = CONV_ROWS * gridDim.x * 256;
        #pragma unroll 4
        for (int i = cid * 256 + tid; i < W_ELEMS4; i += nth)
            conv_chunk(s, d, i);
        return;
    }
    int mt = blockIdx.y - CONV_ROWS;
    if (mt >= g_num_tiles) return;

    extern __shared__ char smem[];
    uint32_t sb = smem_to_u32(smem);
    int lane = tid & 31, wid = tid >> 5;

    int e = g_tile_expert[mt];
    int row_base = mt * TM;
    const __half* B = W + (size_t)e * NTOT * KDIM + (size_t)(blockIdx.x * TN1) * KDIM;

    int* rtok = (int*)(smem + SMEM1_RTOK);
    if (tid < TM) {
        int gr = row_base + tid;
        int cnt = g_counts[e], poff = g_poff[e];
        rtok[tid] = (gr - poff) < cnt ? g_slot_token[gr] : 0;
    }
    __syncthreads();

    // per-thread cp.async: 4 A chunks (128x8) + 2 B chunks (64x8)
    const __half* asrc[4]; const __half* bsrc[2];
    uint32_t adst[4], bdst[2];
    #pragma unroll
    for (int i = 0; i < 4; i++) {
        int f = tid + i * 256;
        int row = f >> 3, c = f & 7;
        asrc[i] = Asrc + (size_t)rtok[row] * KDIM + c * 8;
        adst[i] = sb + SWZ(row * 128 + c * 16);
    }
    #pragma unroll
    for (int i = 0; i < 2; i++) {
        int f = tid + i * 256;
        int row = f >> 3, c = f & 7;
        bsrc[i] = B + (size_t)row * KDIM + c * 8;
        bdst[i] = sb + 16384u + SWZ(row * 128 + c * 16);
    }

    auto issue = [&](int kc, int s) {
        uint32_t off = (uint32_t)s * STAGE1_BYTES;
        size_t koff = (size_t)kc * CK;
        #pragma unroll
        for (int i = 0; i < 4; i++)
            CP_ASYNC16(adst[i] + off, (const void*)(asrc[i] + koff));
        #pragma unroll
        for (int i = 0; i < 2; i++)
            CP_ASYNC16(bdst[i] + off, (const void*)(bsrc[i] + koff));
    };

    // warp tile 32(M) x 32(N); warp grid 4 x 2
    int wm = (wid & 3) * 32;
    int wn = (wid >> 2) * 32;
    int qr = lane >> 2, qc = lane & 3;

    uint32_t arow[2], brow[2];
    #pragma unroll
    for (int mi = 0; mi < 2; mi++)
        arow[mi] = (uint32_t)(wm + mi * 16 + (lane & 15)) * 128u + ((lane >> 4) << 4);
    #pragma unroll
    for (int nb = 0; nb < 2; nb++)
        brow[nb] = (uint32_t)(wn + nb * 16 + ((lane >> 4) & 1) * 8 + (lane & 7)) * 128u
                   + (((lane >> 3) & 1) << 4);

    float c[2][4][4];
    #pragma unroll
    for (int mi = 0; mi < 2; mi++)
        #pragma unroll
        for (int ni = 0; ni < 4; ni++)
            #pragma unroll
            for (int j = 0; j < 4; j++) c[mi][ni][j] = 0.f;

    issue(0, 0); CP_COMMIT();
    issue(1, 1); CP_COMMIT();

    for (int kc = 0; kc < NC; kc++) {
        CP_WAIT(1);
        __syncthreads();
        int nk = kc + STAGES - 1;
        if (nk < NC) issue(nk, nk % STAGES);
        CP_COMMIT();

        uint32_t soff = (uint32_t)(kc % STAGES) * STAGE1_BYTES;
        uint32_t abase = sb + soff;
        uint32_t bbase = sb + soff + 16384u;
        #pragma unroll
        for (int ks = 0; ks < 4; ks++) {
            uint32_t a[2][4], b[2][4];
            #pragma unroll
            for (int mi = 0; mi < 2; mi++)
                ldsm_x4(a[mi][0], a[mi][1], a[mi][2], a[mi][3],
                        abase + SWZ(arow[mi] + ks * 32));
            #pragma unroll
            for (int nb = 0; nb < 2; nb++)
                ldsm_x4(b[nb][0], b[nb][1], b[nb][2], b[nb][3],
                        bbase + SWZ(brow[nb] + ks * 32));
            #pragma unroll
            for (int mi = 0; mi < 2; mi++) {
                #pragma unroll
                for (int nb = 0; nb < 2; nb++) {
                    MMA_F16(c[mi][nb * 2 + 0], a[mi][0], a[mi][1], a[mi][2], a[mi][3],
                            b[nb][0], b[nb][1]);
                    MMA_F16(c[mi][nb * 2 + 1], a[mi][0], a[mi][1], a[mi][2], a[mi][3],
                            b[nb][2], b[nb][3]);
                }
            }
        }
    }

    #pragma unroll
    for (int mi = 0; mi < 2; mi++) {
        #pragma unroll
        for (int ni = 0; ni < 4; ni++) {
            int r0 = row_base + wm + mi * 16 + qr;
            int col = blockIdx.x * TN1 + wn + ni * 8 + 2 * qc;
            float v0 = c[mi][ni][0], v1 = c[mi][ni][1];
            float v2 = c[mi][ni][2], v3 = c[mi][ni][3];
            v0 *= normcdff(v0); v1 *= normcdff(v1);
            v2 *= normcdff(v2); v3 *= normcdff(v3);
            *(__half2*)(g_Hh + (size_t)r0 * NTOT + col)       = __floats2half2_rn(v0, v1);
            *(__half2*)(g_Hh + (size_t)(r0 + 8) * NTOT + col) = __floats2half2_rn(v2, v3);
        }
    }
}

// ---------------- stage 4: GEMM2 (round-10 proven: 128 thr, 64x64 warp tiles) ----------------
// g_Y = g_Hh @ w2h[e]^T     K=4096, Ntot=1024
__global__ void __launch_bounds__(128, 2)
gemm2_f16(const __half* __restrict__ Asrc, const __half* __restrict__ W) {
    constexpr int KDIM = INTER;
    constexpr int NTOT = HID;
    constexpr int NC = KDIM / CK;     // 64

    int tid = threadIdx.x;
    int mt = blockIdx.y;
    if (mt >= g_num_tiles) return;

    extern __shared__ char smem[];
    uint32_t sb = smem_to_u32(smem);
    int lane = tid & 31, wid = tid >> 5;   // 4 warps

    int row_base = mt * TM;
    int e = g_tile_expert[mt];
    const __half* B = W + (size_t)e * NTOT * KDIM + (size_t)(blockIdx.x * TN) * KDIM;

    const __half* asrc[8]; const __half* bsrc[8];
    uint32_t adst[8], bdst[8];
    #pragma unroll
    for (int i = 0; i < 8; i++) {
        int f = tid + i * 128;
        int row = f >> 3, c = f & 7;
        asrc[i] = Asrc + (size_t)(row_base + row) * KDIM + c * 8;
        adst[i] = sb + SWZ(row * 128 + c * 16);
        bsrc[i] = B + (size_t)row * KDIM + c * 8;
        bdst[i] = sb + 16384u + SWZ(row * 128 + c * 16);
    }

    auto issue = [&](int kc, int s) {
        uint32_t off = (uint32_t)s * STAGE_BYTES;
        size_t koff = (size_t)kc * CK;
        #pragma unroll
        for (int i = 0; i < 8; i++) {
            CP_ASYNC16(adst[i] + off, (const void*)(asrc[i] + koff));
            CP_ASYNC16(bdst[i] + off, (const void*)(bsrc[i] + koff));
        }
    };

    int wm = (wid & 1) * 64;
    int wn = (wid >> 1) * 64;
    int qr = lane >> 2, qc = lane & 3;

    uint32_t arow[4], brow[4];
    #pragma unroll
    for (int mi = 0; mi < 4; mi++)
        arow[mi] = (uint32_t)(wm + mi * 16 + (lane & 15)) * 128u + ((lane >> 4) << 4);
    #pragma unroll
    for (int nb = 0; nb < 4; nb++)
        brow[nb] = (uint32_t)(wn + nb * 16 + ((lane >> 4) & 1) * 8 + (lane & 7)) * 128u
                   + (((lane >> 3) & 1) << 4);

    float c[4][8][4];
    #pragma unroll
    for (int mi = 0; mi < 4; mi++)
        #pragma unroll
        for (int ni = 0; ni < 8; ni++)
            #pragma unroll
            for (int j = 0; j < 4; j++) c[mi][ni][j] = 0.f;

    issue(0, 0); CP_COMMIT();
    issue(1, 1); CP_COMMIT();

    for (int kc = 0; kc < NC; kc++) {
        CP_WAIT(1);
        __syncthreads();
        int nk = kc + STAGES - 1;
        if (nk < NC) issue(nk, nk % STAGES);
        CP_COMMIT();

        uint32_t soff = (uint32_t)(kc % STAGES) * STAGE_BYTES;
        uint32_t abase = sb + soff;
        uint32_t bbase = sb + soff + 16384u;
        #pragma unroll
        for (int ks = 0; ks < 4; ks++) {
            uint32_t a[4][4], b[4][4];
            #pragma unroll
            for (int mi = 0; mi < 4; mi++)
                ldsm_x4(a[mi][0], a[mi][1], a[mi][2], a[mi][3],
                        abase + SWZ(arow[mi] + ks * 32));
            #pragma unroll
            for (int nb = 0; nb < 4; nb++)
                ldsm_x4(b[nb][0], b[nb][1], b[nb][2], b[nb][3],
                        bbase + SWZ(brow[nb] + ks * 32));
            #pragma unroll
            for (int mi = 0; mi < 4; mi++) {
                #pragma unroll
                for (int nb = 0; nb < 4; nb++) {
                    MMA_F16(c[mi][nb * 2 + 0], a[mi][0], a[mi][1], a[mi][2], a[mi][3],
                            b[nb][0], b[nb][1]);
                    MMA_F16(c[mi][nb * 2 + 1], a[mi][0], a[mi][1], a[mi][2], a[mi][3],
                            b[nb][2], b[nb][3]);
                }
            }
        }
    }

    #pragma unroll
    for (int mi = 0; mi < 4; mi++) {
        #pragma unroll
        for (int ni = 0; ni < 8; ni++) {
            int r0 = row_base + wm + mi * 16 + qr;
            int col = blockIdx.x * TN + wn + ni * 8 + 2 * qc;
            *(float2*)(g_Y + (size_t)r0 * NTOT + col) =
                make_float2(c[mi][ni][0], c[mi][ni][1]);
            *(float2*)(g_Y + (size_t)(r0 + 8) * NTOT + col) =
                make_float2(c[mi][ni][2], c[mi][ni][3]);
        }
    }
}

// ---------------- stage 5: combine ----------------
__global__ void combine_kernel(float* __restrict__ out) {
    int t = blockIdx.x;
    int s0 = g_tok_slot[2 * t], s1 = g_tok_slot[2 * t + 1];
    float w0 = g_top_w[2 * t], w1 = g_top_w[2 * t + 1];
    const float4* y0 = (const float4*)(g_Y + (size_t)s0 * HID);
    const float4* y1 = (const float4*)(g_Y + (size_t)s1 * HID);
    float4* o = (float4*)(out + (size_t)t * HID);
    int i = threadIdx.x;
    float4 a = y0[i], b = y1[i];
    o[i] = make_float4(w0 * a.x + w1 * b.x, w0 * a.y + w1 * b.y,
                       w0 * a.z + w1 * b.z, w0 * a.w + w1 * b.w);
}

// ---------------- launch ----------------
extern "C" void kernel_launch(void* const* d_in, const int* in_sizes, int n_in,
                              void* d_out, int out_size) {
    const float* x  = (const float*)d_in[0];
    const float* gw = (const float*)d_in[1];
    const float* w1 = (const float*)d_in[2];
    const float* w2 = (const float*)d_in[3];
    float* out = (float*)d_out;
    float* logits = out + (size_t)T_TOK * HID;

    cudaFuncSetAttribute(gemm1_f16, cudaFuncAttributeMaxDynamicSharedMemorySize, SMEM1_TOTAL);
    cudaFuncSetAttribute(gemm2_f16, cudaFuncAttributeMaxDynamicSharedMemorySize, SMEM_TOTAL);

    __half* w1h; cudaGetSymbolAddress((void**)&w1h, g_w1h);
    __half* w2h; cudaGetSymbolAddress((void**)&w2h, g_w2h);
    __half* xh;  cudaGetSymbolAddress((void**)&xh,  g_xh);
    __half* Hh;  cudaGetSymbolAddress((void**)&Hh,  g_Hh);

    init_kernel<<<1, 32>>>();
    router_kernel<<<T_TOK + CONV_BLKS, 256>>>(x, gw, logits, w1);
    scatter_kernel<<<16, 256>>>();
    gemm1_f16<<<dim3(INTER / TN1, MAX_TILES + CONV_ROWS), 256, SMEM1_TOTAL>>>(xh, w1h, w2, w2h);
    gemm2_f16<<<dim3(HID / TN, MAX_TILES), 128, SMEM_TOTAL>>>(Hh, w2h);
    combine_kernel<<<T_TOK, 256>>>(out);
}